// round 8
// baseline (speedup 1.0000x reference)
#include <cuda_runtime.h>
#include <cuda_bf16.h>
#include <cstdint>
#include <cstddef>

// Problem constants (fixed by the reference)
#define NSRC0 200000
#define NDST0 50000
#define NDST1 10000
#define E0    800000
#define E1    160000
#define D     128

#define AS 132  // padded smem row stride (floats): bank = (4*row + col) % 32 -> conflict-free frags

#define NB0 49  // ceil(50000/1024)
#define NB1 10  // ceil(10000/1024)

// ---------------- device scratch (static globals; no allocation) ----------------
__device__ float g_h0[(size_t)NSRC0 * D];
__device__ float g_h1[(size_t)NDST0 * D];
__device__ float g_agg0[(size_t)NDST0 * D];
__device__ float g_agg1[(size_t)NDST1 * D];
__device__ __nv_bfloat16 g_h0b[(size_t)NSRC0 * D];  // bf16 copy for gather
__device__ __nv_bfloat16 g_h1b[(size_t)NDST0 * D];  // bf16 copy for gather

__device__ int g_cnt0[NDST0];
__device__ int g_off0[NDST0 + 1];
__device__ int g_cur0[NDST0];
__device__ int g_esrc0[E0];

__device__ int g_cnt1[NDST1];
__device__ int g_off1[NDST1 + 1];
__device__ int g_cur1[NDST1];
__device__ int g_esrc1[E1];

__device__ int g_bsum[NB0 + NB1];

// ---------------- helpers ----------------
__device__ __forceinline__ uint32_t smem_u32(const void* p) {
    uint32_t a;
    asm("{ .reg .u64 t; cvta.to.shared.u64 t, %1; cvt.u32.u64 %0, t; }" : "=r"(a) : "l"(p));
    return a;
}
__device__ __forceinline__ uint32_t f2tf(float f) {
    uint32_t r;
    asm("cvt.rna.tf32.f32 %0, %1;" : "=r"(r) : "f"(f));
    return r;
}
#define CP_ASYNC16(dst, src) \
    asm volatile("cp.async.cg.shared.global [%0], [%1], 16;" :: "r"(dst), "l"(src) : "memory")
#define CP_COMMIT() asm volatile("cp.async.commit_group;" ::: "memory")
#define CP_WAIT0()  asm volatile("cp.async.wait_group 0;" ::: "memory")

__device__ __forceinline__ void mma_tf32(float d[4], const uint32_t a[4], uint32_t b0, uint32_t b1) {
    asm volatile(
        "mma.sync.aligned.m16n8k8.row.col.f32.tf32.tf32.f32 "
        "{%0,%1,%2,%3}, {%4,%5,%6,%7}, {%8,%9}, {%0,%1,%2,%3};"
        : "+f"(d[0]), "+f"(d[1]), "+f"(d[2]), "+f"(d[3])
        : "r"(a[0]), "r"(a[1]), "r"(a[2]), "r"(a[3]), "r"(b0), "r"(b1));
}

// ---------------- CSR build ----------------
__global__ void zero_counts_kernel() {
    int i = blockIdx.x * blockDim.x + threadIdx.x;
    if (i < NDST0) g_cnt0[i] = 0;
    if (i < NDST1) g_cnt1[i] = 0;
}
__global__ void hist_kernel(const int* __restrict__ dst0, const int* __restrict__ dst1) {
    int i = blockIdx.x * blockDim.x + threadIdx.x;
    if (i < E0) atomicAdd(&g_cnt0[dst0[i]], 1);
    if (i < E1) atomicAdd(&g_cnt1[dst1[i]], 1);
}

// Phase 1: per-block exclusive scan of counts into off (sans base); block totals to g_bsum.
__global__ void scan_blocks_kernel() {
    __shared__ int sums[1024];
    const int b = blockIdx.x;
    const int tid = threadIdx.x;
    const int graph = (b < NB0) ? 0 : 1;
    const int blk = graph ? (b - NB0) : b;
    const int n = graph ? NDST1 : NDST0;
    const int* cnt = graph ? g_cnt1 : g_cnt0;
    int* off = graph ? g_off1 : g_off0;

    const int i = blk * 1024 + tid;
    const int v = (i < n) ? cnt[i] : 0;
    sums[tid] = v;
    __syncthreads();
    #pragma unroll
    for (int d = 1; d < 1024; d <<= 1) {
        int x = (tid >= d) ? sums[tid - d] : 0;
        __syncthreads();
        sums[tid] += x;
        __syncthreads();
    }
    if (i < n) off[i] = sums[tid] - v;
    if (tid == 1023) g_bsum[b] = sums[1023];
}

// Phase 2 (fused tops+apply): each block computes its own base (<=49 adds), applies it.
__global__ void scan_apply_kernel() {
    __shared__ int s_base;
    const int b = blockIdx.x;
    const int tid = threadIdx.x;
    const int graph = (b < NB0) ? 0 : 1;
    const int blk = graph ? (b - NB0) : b;
    const int n = graph ? NDST1 : NDST0;
    int* off = graph ? g_off1 : g_off0;
    int* cur = graph ? g_cur1 : g_cur0;
    if (tid == 0) {
        int base = 0;
        int start = graph ? NB0 : 0;
        for (int j = start; j < b; j++) base += g_bsum[j];
        s_base = base;
        if (b == 0) g_off0[NDST0] = E0;
        if (b == NB0) g_off1[NDST1] = E1;
    }
    __syncthreads();
    const int base = s_base;
    const int i = blk * 1024 + tid;
    if (i < n) {
        int o = off[i] + base;
        off[i] = o;
        cur[i] = o;
    }
}

__global__ void scatter_kernel(const int* __restrict__ src0, const int* __restrict__ dst0,
                               const int* __restrict__ src1, const int* __restrict__ dst1) {
    int i = blockIdx.x * blockDim.x + threadIdx.x;
    if (i < E0) { int pos = atomicAdd(&g_cur0[dst0[i]], 1); g_esrc0[pos] = src0[i]; }
    if (i < E1) { int pos = atomicAdd(&g_cur1[dst1[i]], 1); g_esrc1[pos] = src1[i]; }
}

// ---------------- mean aggregation over bf16 messages, fp32 accumulate ----------------
// One warp per dst node; lane covers 4 columns (uint2 = 4 bf16 per edge-row).
__global__ void aggregate_kernel(const __nv_bfloat16* __restrict__ hb,
                                 const int* __restrict__ off,
                                 const int* __restrict__ esrc, float* __restrict__ agg,
                                 int ndst) {
    int gw = (blockIdx.x * blockDim.x + threadIdx.x) >> 5;
    int lane = threadIdx.x & 31;
    if (gw >= ndst) return;
    int s = off[gw], e = off[gw + 1];
    float4 acc = make_float4(0.f, 0.f, 0.f, 0.f);
    float4 acc2 = make_float4(0.f, 0.f, 0.f, 0.f);
    int i = s;
    for (; i + 2 <= e; i += 2) {
        const uint2* r0 = reinterpret_cast<const uint2*>(hb + (size_t)esrc[i] * D);
        const uint2* r1 = reinterpret_cast<const uint2*>(hb + (size_t)esrc[i + 1] * D);
        uint2 u0 = __ldg(&r0[lane]);
        uint2 u1 = __ldg(&r1[lane]);
        __nv_bfloat162 p0 = *reinterpret_cast<__nv_bfloat162*>(&u0.x);
        __nv_bfloat162 p1 = *reinterpret_cast<__nv_bfloat162*>(&u0.y);
        __nv_bfloat162 q0 = *reinterpret_cast<__nv_bfloat162*>(&u1.x);
        __nv_bfloat162 q1 = *reinterpret_cast<__nv_bfloat162*>(&u1.y);
        acc.x += __bfloat162float(p0.x);  acc.y += __bfloat162float(p0.y);
        acc.z += __bfloat162float(p1.x);  acc.w += __bfloat162float(p1.y);
        acc2.x += __bfloat162float(q0.x); acc2.y += __bfloat162float(q0.y);
        acc2.z += __bfloat162float(q1.x); acc2.w += __bfloat162float(q1.y);
    }
    if (i < e) {
        const uint2* r0 = reinterpret_cast<const uint2*>(hb + (size_t)esrc[i] * D);
        uint2 u0 = __ldg(&r0[lane]);
        __nv_bfloat162 p0 = *reinterpret_cast<__nv_bfloat162*>(&u0.x);
        __nv_bfloat162 p1 = *reinterpret_cast<__nv_bfloat162*>(&u0.y);
        acc.x += __bfloat162float(p0.x); acc.y += __bfloat162float(p0.y);
        acc.z += __bfloat162float(p1.x); acc.w += __bfloat162float(p1.y);
    }
    acc.x += acc2.x; acc.y += acc2.y; acc.z += acc2.z; acc.w += acc2.w;
    float inv = 1.0f / fmaxf((float)(e - s), 1.0f);
    acc.x *= inv; acc.y *= inv; acc.z *= inv; acc.w *= inv;
    reinterpret_cast<float4*>(agg + (size_t)gw * D)[lane] = acc;
}

// ---------------- mma.sync tf32 GEMM ----------------
// ADDC=0: C = maybe_relu(A@B + bias); ADDC=1: C = maybe_relu(C + A@B + bias).
// BF16OUT: also store bf16 copy of result to Cb.
__device__ __forceinline__ void cp_a_tile(float* Asm, const float* __restrict__ A,
                                          int m0, int M, int t) {
    uint32_t sb = smem_u32(Asm);
    #pragma unroll
    for (int j = 0; j < 16; j++) {
        int lin = t + 256 * j;
        int row = lin >> 5;
        int c4  = lin & 31;
        int gm  = m0 + row;
        if (gm < M)
            CP_ASYNC16(sb + (uint32_t)(row * AS + c4 * 4) * 4,
                       A + (size_t)gm * D + c4 * 4);
    }
}

__device__ __forceinline__ void round_a_tile(float* Asm, int t) {
    #pragma unroll
    for (int j = 0; j < 16; j++) {
        int lin = t + 256 * j;
        int row = lin >> 5;
        int c4  = lin & 31;
        float4* p = reinterpret_cast<float4*>(Asm + row * AS + c4 * 4);
        float4 v = *p;
        uint4 r;
        r.x = f2tf(v.x); r.y = f2tf(v.y); r.z = f2tf(v.z); r.w = f2tf(v.w);
        *reinterpret_cast<uint4*>(p) = r;
    }
}

__device__ __forceinline__ void load_b_tile(float* Bsm, const float* __restrict__ W, int t) {
    uint32_t* B32 = reinterpret_cast<uint32_t*>(Bsm);
    #pragma unroll 4
    for (int j = 0; j < 64; j++) {
        int lin = t + 256 * j;
        int k = lin >> 7;
        int n = lin & 127;
        B32[n * AS + k] = f2tf(W[(size_t)k * D + n]);
    }
}

__device__ __forceinline__ void mma_compute(float acc[2][8][4], const float* Asm,
                                            const float* Bsm, int wm, int wn,
                                            int g, int tig) {
    const uint32_t* A32 = reinterpret_cast<const uint32_t*>(Asm);
    const uint32_t* B32 = reinterpret_cast<const uint32_t*>(Bsm);
    #pragma unroll
    for (int k0 = 0; k0 < D; k0 += 8) {
        uint32_t a[2][4];
        #pragma unroll
        for (int mt = 0; mt < 2; mt++) {
            int r = wm + mt * 16 + g;
            a[mt][0] = A32[r * AS + k0 + tig];
            a[mt][1] = A32[(r + 8) * AS + k0 + tig];
            a[mt][2] = A32[r * AS + k0 + tig + 4];
            a[mt][3] = A32[(r + 8) * AS + k0 + tig + 4];
        }
        #pragma unroll
        for (int nt = 0; nt < 8; nt++) {
            int c = wn + nt * 8 + g;
            uint32_t b0 = B32[c * AS + k0 + tig];
            uint32_t b1 = B32[c * AS + k0 + tig + 4];
            mma_tf32(acc[0][nt], a[0], b0, b1);
            mma_tf32(acc[1][nt], a[1], b0, b1);
        }
    }
}

template <int RELU, int ADDC, int BF16OUT>
__device__ __forceinline__ void epilogue(float acc[2][8][4], float* __restrict__ C,
                                         __nv_bfloat16* __restrict__ Cb,
                                         const float* s_bias, int m0, int M,
                                         int wm, int wn, int g, int tig) {
    #pragma unroll
    for (int mt = 0; mt < 2; mt++) {
        #pragma unroll
        for (int half = 0; half < 2; half++) {
            int gm = m0 + wm + mt * 16 + g + half * 8;
            if (gm >= M) continue;
            #pragma unroll
            for (int nt = 0; nt < 8; nt++) {
                int c = wn + nt * 8 + 2 * tig;
                float x = acc[mt][nt][half * 2 + 0] + s_bias[c];
                float y = acc[mt][nt][half * 2 + 1] + s_bias[c + 1];
                if (ADDC) {
                    float2 pv = *reinterpret_cast<const float2*>(C + (size_t)gm * D + c);
                    x += pv.x; y += pv.y;
                }
                if (RELU) { x = fmaxf(x, 0.f); y = fmaxf(y, 0.f); }
                *reinterpret_cast<float2*>(C + (size_t)gm * D + c) = make_float2(x, y);
                if (BF16OUT) {
                    __nv_bfloat162 bv = __floats2bfloat162_rn(x, y);
                    *reinterpret_cast<__nv_bfloat162*>(Cb + (size_t)gm * D + c) = bv;
                }
            }
        }
    }
}

template <int RELU, int ADDC, int BF16OUT>
__global__ void __launch_bounds__(256, 1)
tc_gemm_kernel(const float* __restrict__ A1, const float* __restrict__ B1,
               const float* __restrict__ bias1, float* __restrict__ C,
               __nv_bfloat16* __restrict__ Cb, int M) {
    extern __shared__ float dsm[];
    __shared__ float s_bias[D];

    float* Bs1 = dsm;
    float* Ab0 = Bs1 + 128 * AS;
    float* Ab1 = Ab0 + 128 * AS;

    const int t    = threadIdx.x;
    const int w    = t >> 5;
    const int lane = t & 31;
    const int g    = lane >> 2;
    const int tig  = lane & 3;
    const int wm   = (w >> 1) * 32;
    const int wn   = (w & 1) * 64;

    if (t < D) s_bias[t] = bias1[t];
    load_b_tile(Bs1, B1, t);

    const int ntiles = (M + 127) >> 7;
    float acc[2][8][4];

    int tile = blockIdx.x;
    if (tile < ntiles) cp_a_tile(Ab0, A1, tile << 7, M, t);
    CP_COMMIT();
    __syncthreads();
    int idx = 0;
    for (; tile < ntiles; tile += gridDim.x, idx++) {
        float* cur = (idx & 1) ? Ab1 : Ab0;
        float* nxt = (idx & 1) ? Ab0 : Ab1;
        CP_WAIT0();
        __syncthreads();
        int nt2 = tile + gridDim.x;
        if (nt2 < ntiles) cp_a_tile(nxt, A1, nt2 << 7, M, t);
        CP_COMMIT();
        round_a_tile(cur, t);
        __syncthreads();
        #pragma unroll
        for (int i = 0; i < 2; i++)
            #pragma unroll
            for (int j = 0; j < 8; j++)
                #pragma unroll
                for (int q = 0; q < 4; q++) acc[i][j][q] = 0.f;
        mma_compute(acc, cur, Bs1, wm, wn, g, tig);
        epilogue<RELU, ADDC, BF16OUT>(acc, C, Cb, s_bias, tile << 7, M, wm, wn, g, tig);
        __syncthreads();
    }
}

// ---------------- launch ----------------
extern "C" void kernel_launch(void* const* d_in, const int* in_sizes, int n_in,
                              void* d_out, int out_size) {
    const float* features = (const float*)d_in[0];
    const int*   src0     = (const int*)d_in[1];
    const int*   dst0     = (const int*)d_in[2];
    const int*   src1     = (const int*)d_in[3];
    const int*   dst1     = (const int*)d_in[4];
    const float* W_init   = (const float*)d_in[5];
    const float* b_init   = (const float*)d_in[6];
    const float* W_self   = (const float*)d_in[7];
    const float* b_self   = (const float*)d_in[8];
    const float* W_neigh  = (const float*)d_in[9];
    const float* b_neigh  = (const float*)d_in[10];
    float*       out      = (float*)d_out;

    float *h0, *h1, *agg0, *agg1;
    __nv_bfloat16 *h0b, *h1b;
    int *off0, *esrc0, *off1, *esrc1;
    cudaGetSymbolAddress((void**)&h0, g_h0);
    cudaGetSymbolAddress((void**)&h1, g_h1);
    cudaGetSymbolAddress((void**)&agg0, g_agg0);
    cudaGetSymbolAddress((void**)&agg1, g_agg1);
    cudaGetSymbolAddress((void**)&h0b, g_h0b);
    cudaGetSymbolAddress((void**)&h1b, g_h1b);
    cudaGetSymbolAddress((void**)&off0, g_off0);
    cudaGetSymbolAddress((void**)&esrc0, g_esrc0);
    cudaGetSymbolAddress((void**)&off1, g_off1);
    cudaGetSymbolAddress((void**)&esrc1, g_esrc1);

    const int SMEM_BYTES = 3 * 128 * AS * 4;  // 202752
    static bool s_init = false;
    static cudaStream_t s_side;
    static cudaEvent_t ev_fork, ev_csr, ev_h0, ev_self2, ev_h1, ev_self3;
    if (!s_init) {
        cudaFuncSetAttribute(tc_gemm_kernel<1, 0, 1>, cudaFuncAttributeMaxDynamicSharedMemorySize, SMEM_BYTES);
        cudaFuncSetAttribute(tc_gemm_kernel<0, 0, 0>, cudaFuncAttributeMaxDynamicSharedMemorySize, SMEM_BYTES);
        cudaFuncSetAttribute(tc_gemm_kernel<1, 1, 1>, cudaFuncAttributeMaxDynamicSharedMemorySize, SMEM_BYTES);
        cudaFuncSetAttribute(tc_gemm_kernel<0, 1, 0>, cudaFuncAttributeMaxDynamicSharedMemorySize, SMEM_BYTES);
        cudaStreamCreateWithFlags(&s_side, cudaStreamNonBlocking);
        cudaEventCreateWithFlags(&ev_fork, cudaEventDisableTiming);
        cudaEventCreateWithFlags(&ev_csr, cudaEventDisableTiming);
        cudaEventCreateWithFlags(&ev_h0, cudaEventDisableTiming);
        cudaEventCreateWithFlags(&ev_self2, cudaEventDisableTiming);
        cudaEventCreateWithFlags(&ev_h1, cudaEventDisableTiming);
        cudaEventCreateWithFlags(&ev_self3, cudaEventDisableTiming);
        s_init = true;
    }

    // ---- fork: CSR chain on side stream, GEMM1 on main stream ----
    cudaEventRecord(ev_fork, 0);
    cudaStreamWaitEvent(s_side, ev_fork, 0);

    zero_counts_kernel<<<(NDST0 + 255) / 256, 256, 0, s_side>>>();
    hist_kernel<<<(E0 + 255) / 256, 256, 0, s_side>>>(dst0, dst1);
    scan_blocks_kernel<<<NB0 + NB1, 1024, 0, s_side>>>();
    scan_apply_kernel<<<NB0 + NB1, 1024, 0, s_side>>>();
    scatter_kernel<<<(E0 + 255) / 256, 256, 0, s_side>>>(src0, dst0, src1, dst1);
    cudaEventRecord(ev_csr, s_side);

    // --- layer 0 (main): h0 = relu(features @ W_init + b_init), fp32 + bf16 copies ---
    tc_gemm_kernel<1, 0, 1><<<148, 256, SMEM_BYTES>>>(features, W_init, b_init, h0, h0b, NSRC0);
    cudaEventRecord(ev_h0, 0);

    // --- side: selfGEMM2 (pre-activation partial) concurrent with agg0 ---
    cudaStreamWaitEvent(s_side, ev_h0, 0);
    tc_gemm_kernel<0, 0, 0><<<148, 256, SMEM_BYTES, s_side>>>(h0, W_self, b_self, h1, nullptr, NDST0);
    cudaEventRecord(ev_self2, s_side);

    // --- main: agg0 over bf16 messages (needs h0b + CSR) ---
    cudaStreamWaitEvent(0, ev_csr, 0);
    aggregate_kernel<<<(NDST0 * 32 + 255) / 256, 256>>>(h0b, off0, esrc0, agg0, NDST0);

    // --- main: neighGEMM2 accumulates + relu -> h1 (fp32 + bf16) ---
    cudaStreamWaitEvent(0, ev_self2, 0);
    tc_gemm_kernel<1, 1, 1><<<148, 256, SMEM_BYTES>>>(agg0, W_neigh, b_neigh, h1, h1b, NDST0);
    cudaEventRecord(ev_h1, 0);

    // --- side: selfGEMM3 (pre-activation partial) concurrent with agg1 ---
    cudaStreamWaitEvent(s_side, ev_h1, 0);
    tc_gemm_kernel<0, 0, 0><<<79, 256, SMEM_BYTES, s_side>>>(h1, W_self, b_self, out, nullptr, NDST1);
    cudaEventRecord(ev_self3, s_side);

    // --- main: agg1 over bf16 messages ---
    aggregate_kernel<<<(NDST1 * 32 + 255) / 256, 256>>>(h1b, off1, esrc1, agg1, NDST1);

    // --- main: neighGEMM3 accumulates (no relu) -> out ---
    cudaStreamWaitEvent(0, ev_self3, 0);
    tc_gemm_kernel<0, 1, 0><<<79, 256, SMEM_BYTES>>>(agg1, W_neigh, b_neigh, out, nullptr, NDST1);
}

// round 10
// speedup vs baseline: 1.1666x; 1.1666x over previous
#include <cuda_runtime.h>
#include <cuda_fp16.h>
#include <cstdint>
#include <cstddef>

// Problem constants (fixed by the reference)
#define NSRC0 200000
#define NDST0 50000
#define NDST1 10000
#define E0    800000
#define E1    160000
#define D     128

#define AS 132  // padded smem row stride (floats)

#define NB0 49  // ceil(50000/1024)
#define NB1 10  // ceil(10000/1024)

// ---------------- device scratch (static globals; no allocation) ----------------
// h0/h1 live ONLY in fp16 (g_h0h/g_h1h): exact in tf32, 8x less quant error than bf16.
// fp32 g_h1 is the layer-1 ADDC partial.
__device__ float g_h1[(size_t)NDST0 * D];
__device__ float g_agg0[(size_t)NDST0 * D];
__device__ float g_agg1[(size_t)NDST1 * D];
__device__ __half g_h0h[(size_t)NSRC0 * D];
__device__ __half g_h1h[(size_t)NDST0 * D];

__device__ int g_cnt0[NDST0];
__device__ int g_off0[NDST0 + 1];
__device__ int g_cur0[NDST0];
__device__ int g_esrc0[E0];

__device__ int g_cnt1[NDST1];
__device__ int g_off1[NDST1 + 1];
__device__ int g_cur1[NDST1];
__device__ int g_esrc1[E1];

__device__ int g_bsum[NB0 + NB1];

// ---------------- helpers ----------------
__device__ __forceinline__ uint32_t smem_u32(const void* p) {
    uint32_t a;
    asm("{ .reg .u64 t; cvta.to.shared.u64 t, %1; cvt.u32.u64 %0, t; }" : "=r"(a) : "l"(p));
    return a;
}
__device__ __forceinline__ uint32_t f2tf(float f) {
    uint32_t r;
    asm("cvt.rna.tf32.f32 %0, %1;" : "=r"(r) : "f"(f));
    return r;
}
#define CP_ASYNC16(dst, src) \
    asm volatile("cp.async.cg.shared.global [%0], [%1], 16;" :: "r"(dst), "l"(src) : "memory")
#define CP_COMMIT() asm volatile("cp.async.commit_group;" ::: "memory")
#define CP_WAIT0()  asm volatile("cp.async.wait_group 0;" ::: "memory")

__device__ __forceinline__ void mma_tf32(float d[4], const uint32_t a[4], uint32_t b0, uint32_t b1) {
    asm volatile(
        "mma.sync.aligned.m16n8k8.row.col.f32.tf32.tf32.f32 "
        "{%0,%1,%2,%3}, {%4,%5,%6,%7}, {%8,%9}, {%0,%1,%2,%3};"
        : "+f"(d[0]), "+f"(d[1]), "+f"(d[2]), "+f"(d[3])
        : "r"(a[0]), "r"(a[1]), "r"(a[2]), "r"(a[3]), "r"(b0), "r"(b1));
}

// ---------------- CSR build ----------------
__global__ void zero_counts_kernel() {
    int i = blockIdx.x * blockDim.x + threadIdx.x;
    if (i < NDST0) g_cnt0[i] = 0;
    if (i < NDST1) g_cnt1[i] = 0;
}
__global__ void hist_kernel(const int* __restrict__ dst0, const int* __restrict__ dst1) {
    int i = blockIdx.x * blockDim.x + threadIdx.x;
    if (i < E0) atomicAdd(&g_cnt0[dst0[i]], 1);
    if (i < E1) atomicAdd(&g_cnt1[dst1[i]], 1);
}

__global__ void scan_blocks_kernel() {
    __shared__ int sums[1024];
    const int b = blockIdx.x;
    const int tid = threadIdx.x;
    const int graph = (b < NB0) ? 0 : 1;
    const int blk = graph ? (b - NB0) : b;
    const int n = graph ? NDST1 : NDST0;
    const int* cnt = graph ? g_cnt1 : g_cnt0;
    int* off = graph ? g_off1 : g_off0;

    const int i = blk * 1024 + tid;
    const int v = (i < n) ? cnt[i] : 0;
    sums[tid] = v;
    __syncthreads();
    #pragma unroll
    for (int d = 1; d < 1024; d <<= 1) {
        int x = (tid >= d) ? sums[tid - d] : 0;
        __syncthreads();
        sums[tid] += x;
        __syncthreads();
    }
    if (i < n) off[i] = sums[tid] - v;
    if (tid == 1023) g_bsum[b] = sums[1023];
}

// Fused tops+apply: each block computes its own base (<=49 adds), applies it.
__global__ void scan_apply_kernel() {
    __shared__ int s_base;
    const int b = blockIdx.x;
    const int tid = threadIdx.x;
    const int graph = (b < NB0) ? 0 : 1;
    const int blk = graph ? (b - NB0) : b;
    const int n = graph ? NDST1 : NDST0;
    int* off = graph ? g_off1 : g_off0;
    int* cur = graph ? g_cur1 : g_cur0;
    if (tid == 0) {
        int base = 0;
        int start = graph ? NB0 : 0;
        for (int j = start; j < b; j++) base += g_bsum[j];
        s_base = base;
        if (b == 0) g_off0[NDST0] = E0;
        if (b == NB0) g_off1[NDST1] = E1;
    }
    __syncthreads();
    const int base = s_base;
    const int i = blk * 1024 + tid;
    if (i < n) {
        int o = off[i] + base;
        off[i] = o;
        cur[i] = o;
    }
}

__global__ void scatter_kernel(const int* __restrict__ src0, const int* __restrict__ dst0,
                               const int* __restrict__ src1, const int* __restrict__ dst1) {
    int i = blockIdx.x * blockDim.x + threadIdx.x;
    if (i < E0) { int pos = atomicAdd(&g_cur0[dst0[i]], 1); g_esrc0[pos] = src0[i]; }
    if (i < E1) { int pos = atomicAdd(&g_cur1[dst1[i]], 1); g_esrc1[pos] = src1[i]; }
}

// ---------------- mean aggregation over fp16 messages, fp32 accumulate ----------------
__global__ void aggregate_kernel(const __half* __restrict__ hh,
                                 const int* __restrict__ off,
                                 const int* __restrict__ esrc, float* __restrict__ agg,
                                 int ndst) {
    int gw = (blockIdx.x * blockDim.x + threadIdx.x) >> 5;
    int lane = threadIdx.x & 31;
    if (gw >= ndst) return;
    int s = off[gw], e = off[gw + 1];
    float4 acc = make_float4(0.f, 0.f, 0.f, 0.f);
    float4 acc2 = make_float4(0.f, 0.f, 0.f, 0.f);
    int i = s;
    for (; i + 2 <= e; i += 2) {
        const uint2* r0 = reinterpret_cast<const uint2*>(hh + (size_t)esrc[i] * D);
        const uint2* r1 = reinterpret_cast<const uint2*>(hh + (size_t)esrc[i + 1] * D);
        uint2 u0 = __ldg(&r0[lane]);
        uint2 u1 = __ldg(&r1[lane]);
        float2 p0 = __half22float2(*reinterpret_cast<__half2*>(&u0.x));
        float2 p1 = __half22float2(*reinterpret_cast<__half2*>(&u0.y));
        float2 q0 = __half22float2(*reinterpret_cast<__half2*>(&u1.x));
        float2 q1 = __half22float2(*reinterpret_cast<__half2*>(&u1.y));
        acc.x += p0.x;  acc.y += p0.y;  acc.z += p1.x;  acc.w += p1.y;
        acc2.x += q0.x; acc2.y += q0.y; acc2.z += q1.x; acc2.w += q1.y;
    }
    if (i < e) {
        const uint2* r0 = reinterpret_cast<const uint2*>(hh + (size_t)esrc[i] * D);
        uint2 u0 = __ldg(&r0[lane]);
        float2 p0 = __half22float2(*reinterpret_cast<__half2*>(&u0.x));
        float2 p1 = __half22float2(*reinterpret_cast<__half2*>(&u0.y));
        acc.x += p0.x; acc.y += p0.y; acc.z += p1.x; acc.w += p1.y;
    }
    acc.x += acc2.x; acc.y += acc2.y; acc.z += acc2.z; acc.w += acc2.w;
    float inv = 1.0f / fmaxf((float)(e - s), 1.0f);
    acc.x *= inv; acc.y *= inv; acc.z *= inv; acc.w *= inv;
    reinterpret_cast<float4*>(agg + (size_t)gw * D)[lane] = acc;
}

// ---------------- mma.sync tf32 GEMM ----------------
// AH16: A operand is fp16 in gmem (exactly representable in tf32; simple LDG path).
// ADDC: accumulate into fp32 C partial.  WH16: write ONLY fp16 Ch (else fp32 C).
__device__ __forceinline__ void cp_a_tile(float* Asm, const float* __restrict__ A,
                                          int m0, int M, int t) {
    uint32_t sb = smem_u32(Asm);
    #pragma unroll
    for (int j = 0; j < 16; j++) {
        int lin = t + 256 * j;
        int row = lin >> 5;
        int c4  = lin & 31;
        int gm  = m0 + row;
        if (gm < M)
            CP_ASYNC16(sb + (uint32_t)(row * AS + c4 * 4) * 4,
                       A + (size_t)gm * D + c4 * 4);
    }
}

__device__ __forceinline__ void round_a_tile(float* Asm, int t) {
    #pragma unroll
    for (int j = 0; j < 16; j++) {
        int lin = t + 256 * j;
        int row = lin >> 5;
        int c4  = lin & 31;
        float4* p = reinterpret_cast<float4*>(Asm + row * AS + c4 * 4);
        float4 v = *p;
        uint4 r;
        r.x = f2tf(v.x); r.y = f2tf(v.y); r.z = f2tf(v.z); r.w = f2tf(v.w);
        *reinterpret_cast<uint4*>(p) = r;
    }
}

// Load fp16 A tile, expand to fp32 smem (fp16 exact in tf32 -> no rounding needed).
__device__ __forceinline__ void load_a_f16(float* Asm, const __half* __restrict__ A,
                                           int m0, int M, int t) {
    #pragma unroll
    for (int j = 0; j < 8; j++) {
        int lin = t + 256 * j;          // 0..2047
        int row = lin >> 4;             // 0..127
        int c8  = lin & 15;             // 16B chunk = 8 halves
        int gm  = m0 + row;
        if (gm < M) {
            uint4 u = *reinterpret_cast<const uint4*>(A + (size_t)gm * D + c8 * 8);
            float2 a = __half22float2(*reinterpret_cast<__half2*>(&u.x));
            float2 b = __half22float2(*reinterpret_cast<__half2*>(&u.y));
            float2 c = __half22float2(*reinterpret_cast<__half2*>(&u.z));
            float2 d = __half22float2(*reinterpret_cast<__half2*>(&u.w));
            *reinterpret_cast<float4*>(Asm + row * AS + c8 * 8)     = make_float4(a.x, a.y, b.x, b.y);
            *reinterpret_cast<float4*>(Asm + row * AS + c8 * 8 + 4) = make_float4(c.x, c.y, d.x, d.y);
        }
    }
}

__device__ __forceinline__ void load_b_tile(float* Bsm, const float* __restrict__ W, int t) {
    uint32_t* B32 = reinterpret_cast<uint32_t*>(Bsm);
    #pragma unroll 4
    for (int j = 0; j < 64; j++) {
        int lin = t + 256 * j;
        int k = lin >> 7;
        int n = lin & 127;
        B32[n * AS + k] = f2tf(W[(size_t)k * D + n]);
    }
}

__device__ __forceinline__ void mma_compute(float acc[2][8][4], const float* Asm,
                                            const float* Bsm, int wm, int wn,
                                            int g, int tig) {
    const uint32_t* A32 = reinterpret_cast<const uint32_t*>(Asm);
    const uint32_t* B32 = reinterpret_cast<const uint32_t*>(Bsm);
    #pragma unroll
    for (int k0 = 0; k0 < D; k0 += 8) {
        uint32_t a[2][4];
        #pragma unroll
        for (int mt = 0; mt < 2; mt++) {
            int r = wm + mt * 16 + g;
            a[mt][0] = A32[r * AS + k0 + tig];
            a[mt][1] = A32[(r + 8) * AS + k0 + tig];
            a[mt][2] = A32[r * AS + k0 + tig + 4];
            a[mt][3] = A32[(r + 8) * AS + k0 + tig + 4];
        }
        #pragma unroll
        for (int nt = 0; nt < 8; nt++) {
            int c = wn + nt * 8 + g;
            uint32_t b0 = B32[c * AS + k0 + tig];
            uint32_t b1 = B32[c * AS + k0 + tig + 4];
            mma_tf32(acc[0][nt], a[0], b0, b1);
            mma_tf32(acc[1][nt], a[1], b0, b1);
        }
    }
}

template <int RELU, int ADDC, int WH16>
__device__ __forceinline__ void epilogue(float acc[2][8][4], float* __restrict__ C,
                                         __half* __restrict__ Ch,
                                         const float* s_bias, int m0, int M,
                                         int wm, int wn, int g, int tig) {
    #pragma unroll
    for (int mt = 0; mt < 2; mt++) {
        #pragma unroll
        for (int half_ = 0; half_ < 2; half_++) {
            int gm = m0 + wm + mt * 16 + g + half_ * 8;
            if (gm >= M) continue;
            #pragma unroll
            for (int nt = 0; nt < 8; nt++) {
                int c = wn + nt * 8 + 2 * tig;
                float x = acc[mt][nt][half_ * 2 + 0] + s_bias[c];
                float y = acc[mt][nt][half_ * 2 + 1] + s_bias[c + 1];
                if (ADDC) {
                    float2 pv = *reinterpret_cast<const float2*>(C + (size_t)gm * D + c);
                    x += pv.x; y += pv.y;
                }
                if (RELU) { x = fmaxf(x, 0.f); y = fmaxf(y, 0.f); }
                if (WH16) {
                    __half2 hv = __floats2half2_rn(x, y);
                    *reinterpret_cast<__half2*>(Ch + (size_t)gm * D + c) = hv;
                } else {
                    *reinterpret_cast<float2*>(C + (size_t)gm * D + c) = make_float2(x, y);
                }
            }
        }
    }
}

template <int RELU, int ADDC, int AH16, int WH16>
__global__ void __launch_bounds__(256, 1)
tc_gemm_kernel(const void* __restrict__ Ain, const float* __restrict__ B1,
               const float* __restrict__ bias1, float* __restrict__ C,
               __half* __restrict__ Ch, int M) {
    extern __shared__ float dsm[];
    __shared__ float s_bias[D];

    float* Bs1 = dsm;
    float* Ab0 = Bs1 + 128 * AS;
    float* Ab1 = Ab0 + 128 * AS;   // used by fp32 double-buffer path only

    const int t    = threadIdx.x;
    const int w    = t >> 5;
    const int lane = t & 31;
    const int g    = lane >> 2;
    const int tig  = lane & 3;
    const int wm   = (w >> 1) * 32;
    const int wn   = (w & 1) * 64;

    if (t < D) s_bias[t] = bias1[t];
    load_b_tile(Bs1, B1, t);

    const int ntiles = (M + 127) >> 7;
    float acc[2][8][4];

    if (AH16) {
        const __half* A = (const __half*)Ain;
        __syncthreads();  // B ready
        for (int tile = blockIdx.x; tile < ntiles; tile += gridDim.x) {
            load_a_f16(Ab0, A, tile << 7, M, t);
            __syncthreads();
            #pragma unroll
            for (int i = 0; i < 2; i++)
                #pragma unroll
                for (int j = 0; j < 8; j++)
                    #pragma unroll
                    for (int q = 0; q < 4; q++) acc[i][j][q] = 0.f;
            mma_compute(acc, Ab0, Bs1, wm, wn, g, tig);
            epilogue<RELU, ADDC, WH16>(acc, C, Ch, s_bias, tile << 7, M, wm, wn, g, tig);
            __syncthreads();
        }
    } else {
        const float* A = (const float*)Ain;
        int tile = blockIdx.x;
        if (tile < ntiles) cp_a_tile(Ab0, A, tile << 7, M, t);
        CP_COMMIT();
        __syncthreads();  // B ready
        int idx = 0;
        for (; tile < ntiles; tile += gridDim.x, idx++) {
            float* cur = (idx & 1) ? Ab1 : Ab0;
            float* nxt = (idx & 1) ? Ab0 : Ab1;
            CP_WAIT0();
            __syncthreads();
            int nt2 = tile + gridDim.x;
            if (nt2 < ntiles) cp_a_tile(nxt, A, nt2 << 7, M, t);
            CP_COMMIT();
            round_a_tile(cur, t);
            __syncthreads();
            #pragma unroll
            for (int i = 0; i < 2; i++)
                #pragma unroll
                for (int j = 0; j < 8; j++)
                    #pragma unroll
                    for (int q = 0; q < 4; q++) acc[i][j][q] = 0.f;
            mma_compute(acc, cur, Bs1, wm, wn, g, tig);
            epilogue<RELU, ADDC, WH16>(acc, C, Ch, s_bias, tile << 7, M, wm, wn, g, tig);
            __syncthreads();
        }
    }
}

// ---------------- launch ----------------
extern "C" void kernel_launch(void* const* d_in, const int* in_sizes, int n_in,
                              void* d_out, int out_size) {
    const float* features = (const float*)d_in[0];
    const int*   src0     = (const int*)d_in[1];
    const int*   dst0     = (const int*)d_in[2];
    const int*   src1     = (const int*)d_in[3];
    const int*   dst1     = (const int*)d_in[4];
    const float* W_init   = (const float*)d_in[5];
    const float* b_init   = (const float*)d_in[6];
    const float* W_self   = (const float*)d_in[7];
    const float* b_self   = (const float*)d_in[8];
    const float* W_neigh  = (const float*)d_in[9];
    const float* b_neigh  = (const float*)d_in[10];
    float*       out      = (float*)d_out;

    float *h1, *agg0, *agg1;
    __half *h0h, *h1h;
    int *off0, *esrc0, *off1, *esrc1;
    cudaGetSymbolAddress((void**)&h1, g_h1);
    cudaGetSymbolAddress((void**)&agg0, g_agg0);
    cudaGetSymbolAddress((void**)&agg1, g_agg1);
    cudaGetSymbolAddress((void**)&h0h, g_h0h);
    cudaGetSymbolAddress((void**)&h1h, g_h1h);
    cudaGetSymbolAddress((void**)&off0, g_off0);
    cudaGetSymbolAddress((void**)&esrc0, g_esrc0);
    cudaGetSymbolAddress((void**)&off1, g_off1);
    cudaGetSymbolAddress((void**)&esrc1, g_esrc1);

    const int SMEM_BYTES = 3 * 128 * AS * 4;  // 202752
    static bool s_init = false;
    static cudaStream_t s_side;
    static cudaEvent_t ev_fork, ev_csr, ev_h0, ev_self2, ev_h1, ev_self3;
    if (!s_init) {
        cudaFuncSetAttribute(tc_gemm_kernel<1, 0, 0, 1>, cudaFuncAttributeMaxDynamicSharedMemorySize, SMEM_BYTES);
        cudaFuncSetAttribute(tc_gemm_kernel<0, 0, 1, 0>, cudaFuncAttributeMaxDynamicSharedMemorySize, SMEM_BYTES);
        cudaFuncSetAttribute(tc_gemm_kernel<1, 1, 0, 1>, cudaFuncAttributeMaxDynamicSharedMemorySize, SMEM_BYTES);
        cudaFuncSetAttribute(tc_gemm_kernel<0, 1, 0, 0>, cudaFuncAttributeMaxDynamicSharedMemorySize, SMEM_BYTES);
        cudaStreamCreateWithFlags(&s_side, cudaStreamNonBlocking);
        cudaEventCreateWithFlags(&ev_fork, cudaEventDisableTiming);
        cudaEventCreateWithFlags(&ev_csr, cudaEventDisableTiming);
        cudaEventCreateWithFlags(&ev_h0, cudaEventDisableTiming);
        cudaEventCreateWithFlags(&ev_self2, cudaEventDisableTiming);
        cudaEventCreateWithFlags(&ev_h1, cudaEventDisableTiming);
        cudaEventCreateWithFlags(&ev_self3, cudaEventDisableTiming);
        s_init = true;
    }

    // ---- fork: CSR chain on side stream, GEMM1 on main stream ----
    cudaEventRecord(ev_fork, 0);
    cudaStreamWaitEvent(s_side, ev_fork, 0);

    zero_counts_kernel<<<(NDST0 + 255) / 256, 256, 0, s_side>>>();
    hist_kernel<<<(E0 + 255) / 256, 256, 0, s_side>>>(dst0, dst1);
    scan_blocks_kernel<<<NB0 + NB1, 1024, 0, s_side>>>();
    scan_apply_kernel<<<NB0 + NB1, 1024, 0, s_side>>>();
    scatter_kernel<<<(E0 + 255) / 256, 256, 0, s_side>>>(src0, dst0, src1, dst1);
    cudaEventRecord(ev_csr, s_side);

    // --- layer 0 (main): h0h = fp16(relu(features @ W_init + b_init)), fp16 ONLY ---
    tc_gemm_kernel<1, 0, 0, 1><<<148, 256, SMEM_BYTES>>>(
        features, W_init, b_init, nullptr, h0h, NSRC0);
    cudaEventRecord(ev_h0, 0);

    // --- side: selfGEMM2 (fp16 A, exact in tf32), fp32 partial h1 = h0h@W_self + b_self ---
    cudaStreamWaitEvent(s_side, ev_h0, 0);
    tc_gemm_kernel<0, 0, 1, 0><<<148, 256, SMEM_BYTES, s_side>>>(
        h0h, W_self, b_self, h1, nullptr, NDST0);
    cudaEventRecord(ev_self2, s_side);

    // --- main: agg0 over fp16 messages (needs h0h + CSR); h0h is L2-resident (51 MB) ---
    cudaStreamWaitEvent(0, ev_csr, 0);
    aggregate_kernel<<<(NDST0 * 32 + 255) / 256, 256>>>(h0h, off0, esrc0, agg0, NDST0);

    // --- main: neighGEMM2 reads h1 partial, writes fp16 h1h = relu(...) ---
    cudaStreamWaitEvent(0, ev_self2, 0);
    tc_gemm_kernel<1, 1, 0, 1><<<148, 256, SMEM_BYTES>>>(
        agg0, W_neigh, b_neigh, h1, h1h, NDST0);
    cudaEventRecord(ev_h1, 0);

    // --- side: selfGEMM3 (fp16 A), fp32 partial out = h1h@W_self + b_self ---
    cudaStreamWaitEvent(s_side, ev_h1, 0);
    tc_gemm_kernel<0, 0, 1, 0><<<79, 256, SMEM_BYTES, s_side>>>(
        h1h, W_self, b_self, out, nullptr, NDST1);
    cudaEventRecord(ev_self3, s_side);

    // --- main: agg1 over fp16 messages ---
    aggregate_kernel<<<(NDST1 * 32 + 255) / 256, 256>>>(h1h, off1, esrc1, agg1, NDST1);

    // --- main: neighGEMM3 accumulates into out (no relu, fp32 final) ---
    cudaStreamWaitEvent(0, ev_self3, 0);
    tc_gemm_kernel<0, 1, 0, 0><<<79, 256, SMEM_BYTES>>>(
        agg1, W_neigh, b_neigh, out, nullptr, NDST1);
}

// round 11
// speedup vs baseline: 1.3251x; 1.1359x over previous
#include <cuda_runtime.h>
#include <cuda_fp16.h>
#include <cstdint>
#include <cstddef>

// Problem constants (fixed by the reference)
#define NSRC0 200000
#define NDST0 50000
#define NDST1 10000
#define E0    800000
#define E1    160000
#define D     128

#define AS  132  // fp32 stage row stride (floats)
#define ASH 136  // fp16 tile row stride (halves): bank = (4g+tig)%32 -> conflict-free frags

#define NB0 49  // ceil(50000/1024)
#define NB1 10  // ceil(10000/1024)

// ---------------- device scratch (static globals; no allocation) ----------------
__device__ float g_h1[(size_t)NDST0 * D];    // layer-1 fp32 ADDC partial
__device__ float g_agg0[(size_t)NDST0 * D];
__device__ float g_agg1[(size_t)NDST1 * D];
__device__ __half g_h0h[(size_t)NSRC0 * D];  // h0 lives ONLY in fp16
__device__ __half g_h1h[(size_t)NDST0 * D];  // h1 lives ONLY in fp16

__device__ int g_cnt0[NDST0];
__device__ int g_off0[NDST0 + 1];
__device__ int g_cur0[NDST0];
__device__ int g_esrc0[E0];

__device__ int g_cnt1[NDST1];
__device__ int g_off1[NDST1 + 1];
__device__ int g_cur1[NDST1];
__device__ int g_esrc1[E1];

__device__ int g_bsum[NB0 + NB1];

// ---------------- helpers ----------------
__device__ __forceinline__ uint32_t smem_u32(const void* p) {
    uint32_t a;
    asm("{ .reg .u64 t; cvta.to.shared.u64 t, %1; cvt.u32.u64 %0, t; }" : "=r"(a) : "l"(p));
    return a;
}
#define CP_ASYNC16(dst, src) \
    asm volatile("cp.async.cg.shared.global [%0], [%1], 16;" :: "r"(dst), "l"(src) : "memory")
#define CP_COMMIT() asm volatile("cp.async.commit_group;" ::: "memory")
#define CP_WAIT0()  asm volatile("cp.async.wait_group 0;" ::: "memory")

// m16n8k16 fp16 MMA, fp32 accumulate (same 10-bit mantissa as tf32 -> identical numerics)
__device__ __forceinline__ void mma_f16(float d[4], const uint32_t a[4], uint32_t b0, uint32_t b1) {
    asm volatile(
        "mma.sync.aligned.m16n8k16.row.col.f32.f16.f16.f32 "
        "{%0,%1,%2,%3}, {%4,%5,%6,%7}, {%8,%9}, {%0,%1,%2,%3};"
        : "+f"(d[0]), "+f"(d[1]), "+f"(d[2]), "+f"(d[3])
        : "r"(a[0]), "r"(a[1]), "r"(a[2]), "r"(a[3]), "r"(b0), "r"(b1));
}

// ---------------- CSR build ----------------
__global__ void zero_counts_kernel() {
    int i = blockIdx.x * blockDim.x + threadIdx.x;
    if (i < NDST0) g_cnt0[i] = 0;
    if (i < NDST1) g_cnt1[i] = 0;
}
__global__ void hist_kernel(const int* __restrict__ dst0, const int* __restrict__ dst1) {
    int i = blockIdx.x * blockDim.x + threadIdx.x;
    if (i < E0) atomicAdd(&g_cnt0[dst0[i]], 1);
    if (i < E1) atomicAdd(&g_cnt1[dst1[i]], 1);
}

__global__ void scan_blocks_kernel() {
    __shared__ int sums[1024];
    const int b = blockIdx.x;
    const int tid = threadIdx.x;
    const int graph = (b < NB0) ? 0 : 1;
    const int blk = graph ? (b - NB0) : b;
    const int n = graph ? NDST1 : NDST0;
    const int* cnt = graph ? g_cnt1 : g_cnt0;
    int* off = graph ? g_off1 : g_off0;

    const int i = blk * 1024 + tid;
    const int v = (i < n) ? cnt[i] : 0;
    sums[tid] = v;
    __syncthreads();
    #pragma unroll
    for (int d = 1; d < 1024; d <<= 1) {
        int x = (tid >= d) ? sums[tid - d] : 0;
        __syncthreads();
        sums[tid] += x;
        __syncthreads();
    }
    if (i < n) off[i] = sums[tid] - v;
    if (tid == 1023) g_bsum[b] = sums[1023];
}

// Fused tops+apply: each block computes its own base (<=49 adds), applies it.
__global__ void scan_apply_kernel() {
    __shared__ int s_base;
    const int b = blockIdx.x;
    const int tid = threadIdx.x;
    const int graph = (b < NB0) ? 0 : 1;
    const int blk = graph ? (b - NB0) : b;
    const int n = graph ? NDST1 : NDST0;
    int* off = graph ? g_off1 : g_off0;
    int* cur = graph ? g_cur1 : g_cur0;
    if (tid == 0) {
        int base = 0;
        int start = graph ? NB0 : 0;
        for (int j = start; j < b; j++) base += g_bsum[j];
        s_base = base;
        if (b == 0) g_off0[NDST0] = E0;
        if (b == NB0) g_off1[NDST1] = E1;
    }
    __syncthreads();
    const int base = s_base;
    const int i = blk * 1024 + tid;
    if (i < n) {
        int o = off[i] + base;
        off[i] = o;
        cur[i] = o;
    }
}

__global__ void scatter_kernel(const int* __restrict__ src0, const int* __restrict__ dst0,
                               const int* __restrict__ src1, const int* __restrict__ dst1) {
    int i = blockIdx.x * blockDim.x + threadIdx.x;
    if (i < E0) { int pos = atomicAdd(&g_cur0[dst0[i]], 1); g_esrc0[pos] = src0[i]; }
    if (i < E1) { int pos = atomicAdd(&g_cur1[dst1[i]], 1); g_esrc1[pos] = src1[i]; }
}

// ---------------- mean aggregation over fp16 messages, fp32 accumulate ----------------
__global__ void aggregate_kernel(const __half* __restrict__ hh,
                                 const int* __restrict__ off,
                                 const int* __restrict__ esrc, float* __restrict__ agg,
                                 int ndst) {
    int gw = (blockIdx.x * blockDim.x + threadIdx.x) >> 5;
    int lane = threadIdx.x & 31;
    if (gw >= ndst) return;
    int s = off[gw], e = off[gw + 1];
    float4 acc = make_float4(0.f, 0.f, 0.f, 0.f);
    float4 acc2 = make_float4(0.f, 0.f, 0.f, 0.f);
    int i = s;
    for (; i + 2 <= e; i += 2) {
        const uint2* r0 = reinterpret_cast<const uint2*>(hh + (size_t)esrc[i] * D);
        const uint2* r1 = reinterpret_cast<const uint2*>(hh + (size_t)esrc[i + 1] * D);
        uint2 u0 = __ldg(&r0[lane]);
        uint2 u1 = __ldg(&r1[lane]);
        float2 p0 = __half22float2(*reinterpret_cast<__half2*>(&u0.x));
        float2 p1 = __half22float2(*reinterpret_cast<__half2*>(&u0.y));
        float2 q0 = __half22float2(*reinterpret_cast<__half2*>(&u1.x));
        float2 q1 = __half22float2(*reinterpret_cast<__half2*>(&u1.y));
        acc.x += p0.x;  acc.y += p0.y;  acc.z += p1.x;  acc.w += p1.y;
        acc2.x += q0.x; acc2.y += q0.y; acc2.z += q1.x; acc2.w += q1.y;
    }
    if (i < e) {
        const uint2* r0 = reinterpret_cast<const uint2*>(hh + (size_t)esrc[i] * D);
        uint2 u0 = __ldg(&r0[lane]);
        float2 p0 = __half22float2(*reinterpret_cast<__half2*>(&u0.x));
        float2 p1 = __half22float2(*reinterpret_cast<__half2*>(&u0.y));
        acc.x += p0.x; acc.y += p0.y; acc.z += p1.x; acc.w += p1.y;
    }
    acc.x += acc2.x; acc.y += acc2.y; acc.z += acc2.z; acc.w += acc2.w;
    float inv = 1.0f / fmaxf((float)(e - s), 1.0f);
    acc.x *= inv; acc.y *= inv; acc.z *= inv; acc.w *= inv;
    reinterpret_cast<float4*>(agg + (size_t)gw * D)[lane] = acc;
}

// ---------------- fp16 HMMA GEMM (m16n8k16, fp32 accumulate) ----------------
// AH16: A already fp16 in gmem (direct LDG->STS). Else fp32 A: cp.async stage + convert.
// ADDC: accumulate into fp32 C partial.  WH16: write ONLY fp16 Ch (else fp32 C).

// cp.async fp32 A tile into stage
__device__ __forceinline__ void cp_a_tile(float* Sg, const float* __restrict__ A,
                                          int m0, int M, int t) {
    uint32_t sb = smem_u32(Sg);
    #pragma unroll
    for (int j = 0; j < 16; j++) {
        int lin = t + 256 * j;
        int row = lin >> 5;
        int c4  = lin & 31;
        int gm  = m0 + row;
        if (gm < M)
            CP_ASYNC16(sb + (uint32_t)(row * AS + c4 * 4) * 4,
                       A + (size_t)gm * D + c4 * 4);
    }
}

// stage fp32 -> fp16 tile (RNE; identical mantissa handling to tf32-RNA)
__device__ __forceinline__ void convert_stage(const float* Sg, __half* Af, int t) {
    #pragma unroll
    for (int j = 0; j < 8; j++) {
        int lin = t + 256 * j;      // 0..2047
        int row = lin >> 4;         // 0..127
        int c8  = lin & 15;         // 8-float chunk
        float4 v0 = *reinterpret_cast<const float4*>(Sg + row * AS + c8 * 8);
        float4 v1 = *reinterpret_cast<const float4*>(Sg + row * AS + c8 * 8 + 4);
        uint4 o;
        *reinterpret_cast<__half2*>(&o.x) = __floats2half2_rn(v0.x, v0.y);
        *reinterpret_cast<__half2*>(&o.y) = __floats2half2_rn(v0.z, v0.w);
        *reinterpret_cast<__half2*>(&o.z) = __floats2half2_rn(v1.x, v1.y);
        *reinterpret_cast<__half2*>(&o.w) = __floats2half2_rn(v1.z, v1.w);
        *reinterpret_cast<uint4*>(Af + row * ASH + c8 * 8) = o;
    }
}

// direct fp16 A tile load
__device__ __forceinline__ void load_a_f16(__half* Af, const __half* __restrict__ A,
                                           int m0, int M, int t) {
    #pragma unroll
    for (int j = 0; j < 8; j++) {
        int lin = t + 256 * j;
        int row = lin >> 4;
        int c8  = lin & 15;
        int gm  = m0 + row;
        if (gm < M) {
            uint4 u = *reinterpret_cast<const uint4*>(A + (size_t)gm * D + c8 * 8);
            *reinterpret_cast<uint4*>(Af + row * ASH + c8 * 8) = u;
        }
    }
}

// weights W[k][n] fp32 -> Bs[n][k] fp16 (one time)
__device__ __forceinline__ void load_b_tile(__half* Bs, const float* __restrict__ W, int t) {
    #pragma unroll 4
    for (int j = 0; j < 64; j++) {
        int lin = t + 256 * j;
        int k = lin >> 7;
        int n = lin & 127;
        Bs[n * ASH + k] = __float2half_rn(W[(size_t)k * D + n]);
    }
}

__device__ __forceinline__ void mma_compute(float acc[2][8][4], const __half* Af,
                                            const __half* Bs, int wm, int wn,
                                            int g, int tig) {
    #pragma unroll
    for (int k0 = 0; k0 < D; k0 += 16) {
        uint32_t a[2][4];
        #pragma unroll
        for (int mt = 0; mt < 2; mt++) {
            int r = wm + mt * 16 + g;
            a[mt][0] = *reinterpret_cast<const uint32_t*>(Af + r * ASH + k0 + 2 * tig);
            a[mt][1] = *reinterpret_cast<const uint32_t*>(Af + (r + 8) * ASH + k0 + 2 * tig);
            a[mt][2] = *reinterpret_cast<const uint32_t*>(Af + r * ASH + k0 + 8 + 2 * tig);
            a[mt][3] = *reinterpret_cast<const uint32_t*>(Af + (r + 8) * ASH + k0 + 8 + 2 * tig);
        }
        #pragma unroll
        for (int nt = 0; nt < 8; nt++) {
            int c = wn + nt * 8 + g;
            uint32_t b0 = *reinterpret_cast<const uint32_t*>(Bs + c * ASH + k0 + 2 * tig);
            uint32_t b1 = *reinterpret_cast<const uint32_t*>(Bs + c * ASH + k0 + 8 + 2 * tig);
            mma_f16(acc[0][nt], a[0], b0, b1);
            mma_f16(acc[1][nt], a[1], b0, b1);
        }
    }
}

template <int RELU, int ADDC, int WH16>
__device__ __forceinline__ void epilogue(float acc[2][8][4], float* __restrict__ C,
                                         __half* __restrict__ Ch,
                                         const float* s_bias, int m0, int M,
                                         int wm, int wn, int g, int tig) {
    #pragma unroll
    for (int mt = 0; mt < 2; mt++) {
        #pragma unroll
        for (int half_ = 0; half_ < 2; half_++) {
            int gm = m0 + wm + mt * 16 + g + half_ * 8;
            if (gm >= M) continue;
            #pragma unroll
            for (int nt = 0; nt < 8; nt++) {
                int c = wn + nt * 8 + 2 * tig;
                float x = acc[mt][nt][half_ * 2 + 0] + s_bias[c];
                float y = acc[mt][nt][half_ * 2 + 1] + s_bias[c + 1];
                if (ADDC) {
                    float2 pv = *reinterpret_cast<const float2*>(C + (size_t)gm * D + c);
                    x += pv.x; y += pv.y;
                }
                if (RELU) { x = fmaxf(x, 0.f); y = fmaxf(y, 0.f); }
                if (WH16) {
                    __half2 hv = __floats2half2_rn(x, y);
                    *reinterpret_cast<__half2*>(Ch + (size_t)gm * D + c) = hv;
                } else {
                    *reinterpret_cast<float2*>(C + (size_t)gm * D + c) = make_float2(x, y);
                }
            }
        }
    }
}

template <int RELU, int ADDC, int AH16, int WH16>
__global__ void __launch_bounds__(256, 1)
tc_gemm_kernel(const void* __restrict__ Ain, const float* __restrict__ B1,
               const float* __restrict__ bias1, float* __restrict__ C,
               __half* __restrict__ Ch, int M) {
    extern __shared__ char dsm[];
    __shared__ float s_bias[D];

    __half* Bs = reinterpret_cast<__half*>(dsm);                       // 128*ASH halves = 34816 B
    __half* Af = reinterpret_cast<__half*>(dsm + 128 * ASH * 2);       // 34816 B
    float*  Sg = reinterpret_cast<float*>(dsm + 2 * 128 * ASH * 2);    // fp32 stage 67584 B

    const int t    = threadIdx.x;
    const int w    = t >> 5;
    const int lane = t & 31;
    const int g    = lane >> 2;
    const int tig  = lane & 3;
    const int wm   = (w >> 1) * 32;
    const int wn   = (w & 1) * 64;

    if (t < D) s_bias[t] = bias1[t];
    load_b_tile(Bs, B1, t);

    const int ntiles = (M + 127) >> 7;
    float acc[2][8][4];

    if (AH16) {
        const __half* A = (const __half*)Ain;
        __syncthreads();  // Bs ready
        for (int tile = blockIdx.x; tile < ntiles; tile += gridDim.x) {
            load_a_f16(Af, A, tile << 7, M, t);
            __syncthreads();
            #pragma unroll
            for (int i = 0; i < 2; i++)
                #pragma unroll
                for (int j = 0; j < 8; j++)
                    #pragma unroll
                    for (int q = 0; q < 4; q++) acc[i][j][q] = 0.f;
            mma_compute(acc, Af, Bs, wm, wn, g, tig);
            epilogue<RELU, ADDC, WH16>(acc, C, Ch, s_bias, tile << 7, M, wm, wn, g, tig);
            __syncthreads();
        }
    } else {
        const float* A = (const float*)Ain;
        int tile = blockIdx.x;
        if (tile < ntiles) cp_a_tile(Sg, A, tile << 7, M, t);
        CP_COMMIT();
        __syncthreads();  // Bs ready
        for (; tile < ntiles; tile += gridDim.x) {
            CP_WAIT0();
            __syncthreads();             // stage holds this tile
            convert_stage(Sg, Af, t);    // fp32 -> fp16 tile
            __syncthreads();             // Af ready, stage free
            int nt2 = tile + gridDim.x;
            if (nt2 < ntiles) cp_a_tile(Sg, A, nt2 << 7, M, t);  // overlaps MMA
            CP_COMMIT();
            #pragma unroll
            for (int i = 0; i < 2; i++)
                #pragma unroll
                for (int j = 0; j < 8; j++)
                    #pragma unroll
                    for (int q = 0; q < 4; q++) acc[i][j][q] = 0.f;
            mma_compute(acc, Af, Bs, wm, wn, g, tig);
            epilogue<RELU, ADDC, WH16>(acc, C, Ch, s_bias, tile << 7, M, wm, wn, g, tig);
            __syncthreads();             // all done with Af before next convert
        }
    }
}

// ---------------- launch ----------------
extern "C" void kernel_launch(void* const* d_in, const int* in_sizes, int n_in,
                              void* d_out, int out_size) {
    const float* features = (const float*)d_in[0];
    const int*   src0     = (const int*)d_in[1];
    const int*   dst0     = (const int*)d_in[2];
    const int*   src1     = (const int*)d_in[3];
    const int*   dst1     = (const int*)d_in[4];
    const float* W_init   = (const float*)d_in[5];
    const float* b_init   = (const float*)d_in[6];
    const float* W_self   = (const float*)d_in[7];
    const float* b_self   = (const float*)d_in[8];
    const float* W_neigh  = (const float*)d_in[9];
    const float* b_neigh  = (const float*)d_in[10];
    float*       out      = (float*)d_out;

    float *h1, *agg0, *agg1;
    __half *h0h, *h1h;
    int *off0, *esrc0, *off1, *esrc1;
    cudaGetSymbolAddress((void**)&h1, g_h1);
    cudaGetSymbolAddress((void**)&agg0, g_agg0);
    cudaGetSymbolAddress((void**)&agg1, g_agg1);
    cudaGetSymbolAddress((void**)&h0h, g_h0h);
    cudaGetSymbolAddress((void**)&h1h, g_h1h);
    cudaGetSymbolAddress((void**)&off0, g_off0);
    cudaGetSymbolAddress((void**)&esrc0, g_esrc0);
    cudaGetSymbolAddress((void**)&off1, g_off1);
    cudaGetSymbolAddress((void**)&esrc1, g_esrc1);

    const int SMEM_BYTES = 2 * 128 * ASH * 2 + 128 * AS * 4;  // 34816*2 + 67584 = 137216
    static bool s_init = false;
    static cudaStream_t s_side;
    static cudaEvent_t ev_fork, ev_csr, ev_h0, ev_self2, ev_h1, ev_self3;
    if (!s_init) {
        cudaFuncSetAttribute(tc_gemm_kernel<1, 0, 0, 1>, cudaFuncAttributeMaxDynamicSharedMemorySize, SMEM_BYTES);
        cudaFuncSetAttribute(tc_gemm_kernel<0, 0, 1, 0>, cudaFuncAttributeMaxDynamicSharedMemorySize, SMEM_BYTES);
        cudaFuncSetAttribute(tc_gemm_kernel<1, 1, 0, 1>, cudaFuncAttributeMaxDynamicSharedMemorySize, SMEM_BYTES);
        cudaFuncSetAttribute(tc_gemm_kernel<0, 1, 0, 0>, cudaFuncAttributeMaxDynamicSharedMemorySize, SMEM_BYTES);
        cudaStreamCreateWithFlags(&s_side, cudaStreamNonBlocking);
        cudaEventCreateWithFlags(&ev_fork, cudaEventDisableTiming);
        cudaEventCreateWithFlags(&ev_csr, cudaEventDisableTiming);
        cudaEventCreateWithFlags(&ev_h0, cudaEventDisableTiming);
        cudaEventCreateWithFlags(&ev_self2, cudaEventDisableTiming);
        cudaEventCreateWithFlags(&ev_h1, cudaEventDisableTiming);
        cudaEventCreateWithFlags(&ev_self3, cudaEventDisableTiming);
        s_init = true;
    }

    // ---- fork: CSR chain on side stream, GEMM1 on main stream ----
    // Enqueue order puts GEMM1 4th so ncu's profiled launch is GEMM1 next round.
    cudaEventRecord(ev_fork, 0);
    cudaStreamWaitEvent(s_side, ev_fork, 0);

    zero_counts_kernel<<<(NDST0 + 255) / 256, 256, 0, s_side>>>();           // #1
    hist_kernel<<<(E0 + 255) / 256, 256, 0, s_side>>>(dst0, dst1);           // #2
    scan_blocks_kernel<<<NB0 + NB1, 1024, 0, s_side>>>();                    // #3

    // --- layer 0 (main): h0h = fp16(relu(features @ W_init + b_init)) ---  // #4 (profiled)
    tc_gemm_kernel<1, 0, 0, 1><<<148, 256, SMEM_BYTES>>>(
        features, W_init, b_init, nullptr, h0h, NSRC0);
    cudaEventRecord(ev_h0, 0);

    scan_apply_kernel<<<NB0 + NB1, 1024, 0, s_side>>>();                     // #5
    scatter_kernel<<<(E0 + 255) / 256, 256, 0, s_side>>>(src0, dst0, src1, dst1);  // #6
    cudaEventRecord(ev_csr, s_side);

    // --- side: selfGEMM2 (fp16 A), fp32 partial h1 = h0h@W_self + b_self ---
    cudaStreamWaitEvent(s_side, ev_h0, 0);
    tc_gemm_kernel<0, 0, 1, 0><<<148, 256, SMEM_BYTES, s_side>>>(
        h0h, W_self, b_self, h1, nullptr, NDST0);
    cudaEventRecord(ev_self2, s_side);

    // --- main: agg0 over fp16 messages (needs h0h + CSR) ---
    cudaStreamWaitEvent(0, ev_csr, 0);
    aggregate_kernel<<<(NDST0 * 32 + 255) / 256, 256>>>(h0h, off0, esrc0, agg0, NDST0);

    // --- main: neighGEMM2 reads h1 partial, writes fp16 h1h = relu(...) ---
    cudaStreamWaitEvent(0, ev_self2, 0);
    tc_gemm_kernel<1, 1, 0, 1><<<148, 256, SMEM_BYTES>>>(
        agg0, W_neigh, b_neigh, h1, h1h, NDST0);
    cudaEventRecord(ev_h1, 0);

    // --- side: selfGEMM3 (fp16 A), fp32 partial out = h1h@W_self + b_self ---
    cudaStreamWaitEvent(s_side, ev_h1, 0);
    tc_gemm_kernel<0, 0, 1, 0><<<79, 256, SMEM_BYTES, s_side>>>(
        h1h, W_self, b_self, out, nullptr, NDST1);
    cudaEventRecord(ev_self3, s_side);

    // --- main: agg1 over fp16 messages ---
    aggregate_kernel<<<(NDST1 * 32 + 255) / 256, 256>>>(h1h, off1, esrc1, agg1, NDST1);

    // --- main: neighGEMM3 accumulates into out (no relu, fp32 final) ---
    cudaStreamWaitEvent(0, ev_self3, 0);
    tc_gemm_kernel<0, 1, 0, 0><<<79, 256, SMEM_BYTES>>>(
        agg1, W_neigh, b_neigh, out, nullptr, NDST1);
}